// round 14
// baseline (speedup 1.0000x reference)
#include <cuda_runtime.h>
#include <cuda_bf16.h>
#include <math.h>
#include <stdint.h>

#define BB   4
#define CC   256
#define NSP  4096
#define EPSN 2.220446049250313e-16f

// ------------------------- device scratch ------------------------------------
__device__ float g_ymean[BB * CC];
__device__ __nv_bfloat16 g_Xt[(size_t)BB * NSP * CC];
__device__ __nv_bfloat16 g_Yt[(size_t)BB * NSP * CC];
__device__ __nv_bfloat16 g_S[(size_t)BB * NSP * NSP];   // 128 MB similarity (bf16)
__device__ float g_maxA[BB * NSP];

// ------------------------- helpers -------------------------------------------
__device__ __forceinline__ uint32_t pack_bf16x2(float lo, float hi) {
    uint32_t r;
    asm("cvt.rn.bf16x2.f32 %0, %1, %2;" : "=r"(r) : "f"(hi), "f"(lo));
    return r;
}
__device__ __forceinline__ uint32_t max_bf16x2(uint32_t a, uint32_t b) {
    uint32_t r;
    asm("max.bf16x2 %0, %1, %2;" : "=r"(r) : "r"(a), "r"(b));
    return r;
}
#define CP_ASYNC16(dst, src) \
    asm volatile("cp.async.cg.shared.global [%0], [%1], 16;" :: "r"(dst), "l"(src))
#define CP_COMMIT() asm volatile("cp.async.commit_group;")
#define CP_WAIT(n)  asm volatile("cp.async.wait_group %0;" :: "n"(n))

__device__ __forceinline__ uint32_t smem_u32(const void* p) {
    uint32_t a;
    asm("{ .reg .u64 t; cvta.to.shared.u64 t, %1; cvt.u32.u64 %0, t; }" : "=r"(a) : "l"(p));
    return a;
}
__device__ __forceinline__ void mma_bf16(float* c, uint32_t a0, uint32_t a1,
                                         uint32_t a2, uint32_t a3,
                                         uint32_t b0, uint32_t b1) {
    asm volatile(
        "mma.sync.aligned.m16n8k16.row.col.f32.bf16.bf16.f32 "
        "{%0,%1,%2,%3}, {%4,%5,%6,%7}, {%8,%9}, {%0,%1,%2,%3};"
        : "+f"(c[0]), "+f"(c[1]), "+f"(c[2]), "+f"(c[3])
        : "r"(a0), "r"(a1), "r"(a2), "r"(a3), "r"(b0), "r"(b1));
}

// --- packed f32x2 ops (Blackwell) ---
__device__ __forceinline__ uint64_t pk2(uint32_t lo, uint32_t hi) {
    uint64_t d; asm("mov.b64 %0, {%1,%2};" : "=l"(d) : "r"(lo), "r"(hi)); return d;
}
__device__ __forceinline__ void upk2(uint64_t v, uint32_t& lo, uint32_t& hi) {
    asm("mov.b64 {%0,%1}, %2;" : "=r"(lo), "=r"(hi) : "l"(v));
}
__device__ __forceinline__ uint64_t fma2(uint64_t a, uint64_t b, uint64_t c) {
    uint64_t d; asm("fma.rn.f32x2 %0, %1, %2, %3;" : "=l"(d) : "l"(a), "l"(b), "l"(c)); return d;
}
__device__ __forceinline__ uint64_t add2(uint64_t a, uint64_t b) {
    uint64_t d; asm("add.rn.f32x2 %0, %1, %2;" : "=l"(d) : "l"(a), "l"(b)); return d;
}
__device__ __forceinline__ uint64_t dupf(float x) {
    uint32_t u = __float_as_uint(x); return pk2(u, u);
}

// ------------------------- 1) per-channel spatial mean of Y ------------------
__global__ void k_mean(const float* __restrict__ Y) {
    int bc = blockIdx.x, tid = threadIdx.x;
    const float* p = Y + (size_t)bc * NSP;
    float s = 0.0f;
#pragma unroll
    for (int j = 0; j < 16; j++) s += p[tid + j * 256];
    __shared__ float red[256];
    red[tid] = s; __syncthreads();
    for (int off = 128; off > 0; off >>= 1) {
        if (tid < off) red[tid] += red[tid + off];
        __syncthreads();
    }
    if (tid == 0) g_ymean[bc] = red[0] * (1.0f / NSP);
}

// --------- 2) fused: center, norm, transpose to [n][c'] bf16 -----------------
#define PREP_SMEM (2 * 256 * 33 * 4)
__global__ void __launch_bounds__(256) k_prep(const float* __restrict__ X,
                                              const float* __restrict__ Y) {
    extern __shared__ float dsm[];
    float* fx = dsm;                 // [256][33]
    float* fy = dsm + 256 * 33;      // [256][33]
    __shared__ float psx[8][32], psy[8][32], rnx_s[32], rny_s[32];

    int b = blockIdx.y;
    int n0 = blockIdx.x * 32;
    int tid = threadIdx.x;
    int n = tid & 31;
    int c8 = tid >> 5;               // 0..7

    float sx = 0.0f, sy = 0.0f;
#pragma unroll 4
    for (int pass = 0; pass < 32; pass++) {
        int c = pass * 8 + c8;
        float m = g_ymean[b * CC + c];
        size_t src = ((size_t)(b * CC + c) << 12) + n0 + n;
        float xv = X[src] - m;
        float yv = Y[src] - m;
        fx[c * 33 + n] = xv;
        fy[c * 33 + n] = yv;
        sx = fmaf(xv, xv, sx);
        sy = fmaf(yv, yv, sy);
    }
    psx[c8][n] = sx;
    psy[c8][n] = sy;
    __syncthreads();
    if (tid < 32) {
        float tx = 0.0f, ty = 0.0f;
#pragma unroll
        for (int i = 0; i < 8; i++) { tx += psx[i][tid]; ty += psy[i][tid]; }
        rnx_s[tid] = 1.0f / (sqrtf(tx) + EPSN);
        rny_s[tid] = 1.0f / (sqrtf(ty) + EPSN);
    }
    __syncthreads();

    // Paired writes: channels (2q, 2q+1) land at adjacent permuted slots.
    int k0 = (tid & 15) * 2;
    int pe = (((k0 >> 1) & 3) << 3) | (((k0 >> 4) & 1) << 2) | (((k0 >> 3) & 1) << 1);
#pragma unroll
    for (int pass = 0; pass < 2; pass++) {
        int nn = (tid >> 4) + pass * 16;     // 0..31
        float rx = rnx_s[nn], ry = rny_s[nn];
        size_t base = ((size_t)((b << 12) + n0 + nn)) << 8;
#pragma unroll
        for (int cg = 0; cg < 8; cg++) {
            int c = k0 + cg * 32;
            int cp = (cg * 32) | pe;
            uint32_t vx = pack_bf16x2(fx[c * 33 + nn] * rx, fx[(c + 1) * 33 + nn] * rx);
            uint32_t vy = pack_bf16x2(fy[c * 33 + nn] * ry, fy[(c + 1) * 33 + nn] * ry);
            *(uint32_t*)(g_Xt + base + cp) = vx;
            *(uint32_t*)(g_Yt + base + cp) = vy;
        }
    }
}

// ------------------- 3) bf16 mma.sync GEMM, 64x64 warp tiles -----------------
#define TILE_B   16384          // bytes per 128x64 bf16 tile
#define SMA(st)  ((st) * 2 * TILE_B)
#define SMB(st)  ((st) * 2 * TILE_B + TILE_B)
#define SM_TOT   (4 * TILE_B)   // 64 KB

__global__ void __launch_bounds__(128, 2) k_gemm_mma() {
    extern __shared__ char sm[];
    uint32_t sb = smem_u32(sm);
    int tid = threadIdx.x;
    int l = tid & 31, w = tid >> 5;
    int warpM = w >> 1, warpN = w & 1;
    int b = blockIdx.z;
    int n0 = blockIdx.y * 128, m0 = blockIdx.x * 128;

    const char* Ab = (const char*)(g_Xt + ((size_t)((b << 12) + n0)) * CC);
    const char* Bb = (const char*)(g_Yt + ((size_t)((b << 12) + m0)) * CC);

    int lr = tid >> 3;          // 0..15: row within 16-row pass
    int lc = tid & 7;           // 16B chunk within 128B row

    float acc[4][8][4];
#pragma unroll
    for (int i = 0; i < 4; i++)
#pragma unroll
        for (int j = 0; j < 8; j++)
#pragma unroll
            for (int q = 0; q < 4; q++) acc[i][j][q] = 0.0f;

    auto load = [&](int kc, int st) {
#pragma unroll
        for (int it = 0; it < 8; it++) {
            int row = lr + it * 16;
            uint32_t sw = (uint32_t)((lc ^ ((row & 1) << 2)) << 4);
            CP_ASYNC16(sb + SMA(st) + row * 128 + sw, Ab + (size_t)row * 512 + kc * 128 + lc * 16);
            CP_ASYNC16(sb + SMB(st) + row * 128 + sw, Bb + (size_t)row * 512 + kc * 128 + lc * 16);
        }
    };

    load(0, 0); CP_COMMIT();

    for (int kc = 0; kc < 4; kc++) {
        int st = kc & 1;
        CP_WAIT(0);
        __syncthreads();
        if (kc + 1 < 4) { load(kc + 1, st ^ 1); CP_COMMIT(); }

#pragma unroll
        for (int g = 0; g < 2; g++) {
            uint4 Af[4][2];
            uint4 Bf[8];
#pragma unroll
            for (int mi = 0; mi < 4; mi++)
#pragma unroll
                for (int h = 0; h < 2; h++) {
                    int r = warpM * 64 + mi * 16 + (l >> 2) + h * 8;
                    int ch = (g * 4 + (l & 3)) ^ ((r & 1) << 2);
                    Af[mi][h] = *(const uint4*)(sm + SMA(st) + r * 128 + ch * 16);
                }
#pragma unroll
            for (int ni = 0; ni < 8; ni++) {
                int r = warpN * 64 + ni * 8 + (l >> 2);
                int ch = (g * 4 + (l & 3)) ^ ((r & 1) << 2);
                Bf[ni] = *(const uint4*)(sm + SMB(st) + r * 128 + ch * 16);
            }

#pragma unroll
            for (int mi = 0; mi < 4; mi++)
#pragma unroll
                for (int ni = 0; ni < 8; ni++)
                    mma_bf16(acc[mi][ni], Af[mi][0].x, Af[mi][1].x, Af[mi][0].y, Af[mi][1].y,
                             Bf[ni].x, Bf[ni].y);
#pragma unroll
            for (int mi = 0; mi < 4; mi++)
#pragma unroll
                for (int ni = 0; ni < 8; ni++)
                    mma_bf16(acc[mi][ni], Af[mi][0].z, Af[mi][1].z, Af[mi][0].w, Af[mi][1].w,
                             Bf[ni].z, Bf[ni].w);
        }
    }

    // --- epilogue: write S as bf16 (default caching: keep tail in L2) ---
    __nv_bfloat16* Sp = g_S + (size_t)b * NSP * NSP;
#pragma unroll
    for (int mi = 0; mi < 4; mi++) {
        int r = n0 + warpM * 64 + mi * 16 + (l >> 2);
#pragma unroll
        for (int ni = 0; ni < 8; ni++) {
            int cg = m0 + warpN * 64 + ni * 8 + ((l & 3) << 1);
            *(uint32_t*)(Sp + (size_t)r * NSP + cg)       = pack_bf16x2(acc[mi][ni][0], acc[mi][ni][1]);
            *(uint32_t*)(Sp + (size_t)(r + 8) * NSP + cg) = pack_bf16x2(acc[mi][ni][2], acc[mi][ni][3]);
        }
    }
}

// ------------------------- 4) per-row: max (bf16x2) -> exp-sum ---------------
// Rows processed in REVERSE write order: most-recently-written S rows (still
// L2-resident after the GEMM) are consumed first.
__global__ void k_reduce() {
    int row = (BB * NSP - 1) - blockIdx.x;
    int tid = threadIdx.x;
    int l = tid & 31, w = tid >> 5;
    const uint4* p = (const uint4*)(g_S + (size_t)row * NSP);
    uint4 v0 = __ldcs(p + tid * 2), v1 = __ldcs(p + tid * 2 + 1);
    uint32_t u[8] = { v0.x, v0.y, v0.z, v0.w, v1.x, v1.y, v1.z, v1.w };

    // --- row max via packed bf16x2 max ---
    uint32_t mx2 = u[0];
#pragma unroll
    for (int j = 1; j < 8; j++) mx2 = max_bf16x2(mx2, u[j]);
    float mx = fmaxf(__uint_as_float(mx2 << 16),
                     __uint_as_float(mx2 & 0xffff0000u));
#pragma unroll
    for (int off = 16; off > 0; off >>= 1)
        mx = fmaxf(mx, __shfl_xor_sync(0xffffffffu, mx, off));
    __shared__ float red[8];
    __shared__ float bcast;
    if (l == 0) red[w] = mx;
    __syncthreads();
    if (tid == 0) {
        float m = red[0];
#pragma unroll
        for (int i = 1; i < 8; i++) m = fmaxf(m, red[i]);
        bcast = m;
    }
    __syncthreads();
    float smax = bcast;

    // weight = 2^(s*kk2 + c2), packed f32x2 math
    float kk2 = 14.4269504089f / (1.001f - smax);          // 10*log2(e)/c
    float c2f = (0.001f - smax) * kk2;
    const float MAGIC = 12582912.0f;                       // 1.5 * 2^23
    const int ZCLAMP = 0x4B400000 - 126;                   // bits(MAGIC) - 126

    uint64_t K2  = dupf(kk2), C2 = dupf(c2f), M2 = dupf(MAGIC);
    uint64_t NM2 = dupf(-MAGIC), N1 = dupf(-1.0f);
    uint64_t P4 = dupf(9.618129e-3f), P3 = dupf(5.550411e-2f);
    uint64_t P2 = dupf(2.402265e-1f), P1 = dupf(6.931472e-1f), ONE = dupf(1.0f);

    float sumA = 0.0f, sumB = 0.0f;
#pragma unroll
    for (int j = 0; j < 8; j++) {
        uint64_t s2 = pk2(u[j] << 16, u[j] & 0xffff0000u);
        uint64_t y2 = fma2(s2, K2, C2);
        uint64_t z2 = add2(y2, M2);        // magic-rounded
        uint64_t d2 = add2(z2, NM2);       // rint(y)
        uint64_t t2 = fma2(d2, N1, y2);    // frac in [-0.5, 0.5]
        uint64_t q2 = fma2(t2, P4, P3);
        q2 = fma2(t2, q2, P2);
        q2 = fma2(t2, q2, P1);
        q2 = fma2(t2, q2, ONE);
        uint32_t zl, zh, ql, qh;
        upk2(z2, zl, zh);
        upk2(q2, ql, qh);
        int kl = max((int)zl, ZCLAMP);
        int kh = max((int)zh, ZCLAMP);
        uint32_t scl = ((uint32_t)kl << 23) + 0x3F800000u;
        uint32_t sch = ((uint32_t)kh << 23) + 0x3F800000u;
        sumA = fmaf(__uint_as_float(ql), __uint_as_float(scl), sumA);
        sumB = fmaf(__uint_as_float(qh), __uint_as_float(sch), sumB);
    }
    float sum = sumA + sumB;
#pragma unroll
    for (int off = 16; off > 0; off >>= 1)
        sum += __shfl_xor_sync(0xffffffffu, sum, off);
    if (l == 0) red[w] = sum;
    __syncthreads();
    if (tid == 0) {
        float tsum = 0.0f;
#pragma unroll
        for (int i = 0; i < 8; i++) tsum += red[i];
        g_maxA[row] = exp2f(0.001f * kk2) / tsum;
    }
}

// ------------------------- 5) loss -------------------------------------------
__global__ void k_final(float* __restrict__ out) {
    int b = blockIdx.x, tid = threadIdx.x;
    float s = 0.0f;
#pragma unroll
    for (int j = 0; j < 16; j++) s += g_maxA[b * NSP + tid + j * 256];
    __shared__ float red[256];
    red[tid] = s; __syncthreads();
    for (int off = 128; off > 0; off >>= 1) {
        if (tid < off) red[tid] += red[tid + off];
        __syncthreads();
    }
    if (tid == 0) out[b] = -logf(red[0] * (1.0f / NSP));
}

// ------------------------- launch --------------------------------------------
extern "C" void kernel_launch(void* const* d_in, const int* in_sizes, int n_in,
                              void* d_out, int out_size) {
    const float* X = (const float*)d_in[0];
    const float* Y = (const float*)d_in[1];
    float* out = (float*)d_out;

    cudaFuncSetAttribute(k_prep, cudaFuncAttributeMaxDynamicSharedMemorySize, PREP_SMEM);
    cudaFuncSetAttribute(k_gemm_mma, cudaFuncAttributeMaxDynamicSharedMemorySize, SM_TOT);

    k_mean<<<BB * CC, 256>>>(Y);
    k_prep<<<dim3(NSP / 32, BB), 256, PREP_SMEM>>>(X, Y);
    k_gemm_mma<<<dim3(NSP / 128, NSP / 128, BB), 128, SM_TOT>>>();
    k_reduce<<<BB * NSP, 256>>>();
    k_final<<<BB, 256>>>(out);
}

// round 15
// speedup vs baseline: 1.0738x; 1.0738x over previous
#include <cuda_runtime.h>
#include <cuda_bf16.h>
#include <math.h>
#include <stdint.h>

#define BB   4
#define CC   256
#define NSP  4096
#define EPSN 2.220446049250313e-16f

// ------------------------- device scratch ------------------------------------
__device__ float g_ymean[BB * CC];
__device__ __nv_bfloat16 g_Xt[(size_t)BB * NSP * CC];
__device__ __nv_bfloat16 g_Yt[(size_t)BB * NSP * CC];
__device__ __nv_bfloat16 g_S[(size_t)BB * NSP * NSP];   // 128 MB similarity (bf16)
__device__ float g_maxA[BB * NSP];

// ------------------------- helpers -------------------------------------------
__device__ __forceinline__ uint32_t pack_bf16x2(float lo, float hi) {
    uint32_t r;
    asm("cvt.rn.bf16x2.f32 %0, %1, %2;" : "=r"(r) : "f"(hi), "f"(lo));
    return r;
}
__device__ __forceinline__ uint32_t max_bf16x2(uint32_t a, uint32_t b) {
    uint32_t r;
    asm("max.bf16x2 %0, %1, %2;" : "=r"(r) : "r"(a), "r"(b));
    return r;
}
#define CP_ASYNC16(dst, src) \
    asm volatile("cp.async.cg.shared.global [%0], [%1], 16;" :: "r"(dst), "l"(src))
#define CP_COMMIT() asm volatile("cp.async.commit_group;")
#define CP_WAIT(n)  asm volatile("cp.async.wait_group %0;" :: "n"(n))

__device__ __forceinline__ uint32_t smem_u32(const void* p) {
    uint32_t a;
    asm("{ .reg .u64 t; cvta.to.shared.u64 t, %1; cvt.u32.u64 %0, t; }" : "=r"(a) : "l"(p));
    return a;
}
__device__ __forceinline__ void mma_bf16(float* c, uint32_t a0, uint32_t a1,
                                         uint32_t a2, uint32_t a3,
                                         uint32_t b0, uint32_t b1) {
    asm volatile(
        "mma.sync.aligned.m16n8k16.row.col.f32.bf16.bf16.f32 "
        "{%0,%1,%2,%3}, {%4,%5,%6,%7}, {%8,%9}, {%0,%1,%2,%3};"
        : "+f"(c[0]), "+f"(c[1]), "+f"(c[2]), "+f"(c[3])
        : "r"(a0), "r"(a1), "r"(a2), "r"(a3), "r"(b0), "r"(b1));
}

// --- packed f32x2 ops (Blackwell) ---
__device__ __forceinline__ uint64_t pk2(uint32_t lo, uint32_t hi) {
    uint64_t d; asm("mov.b64 %0, {%1,%2};" : "=l"(d) : "r"(lo), "r"(hi)); return d;
}
__device__ __forceinline__ void upk2(uint64_t v, uint32_t& lo, uint32_t& hi) {
    asm("mov.b64 {%0,%1}, %2;" : "=r"(lo), "=r"(hi) : "l"(v));
}
__device__ __forceinline__ uint64_t fma2(uint64_t a, uint64_t b, uint64_t c) {
    uint64_t d; asm("fma.rn.f32x2 %0, %1, %2, %3;" : "=l"(d) : "l"(a), "l"(b), "l"(c)); return d;
}
__device__ __forceinline__ uint64_t add2(uint64_t a, uint64_t b) {
    uint64_t d; asm("add.rn.f32x2 %0, %1, %2;" : "=l"(d) : "l"(a), "l"(b)); return d;
}
__device__ __forceinline__ uint64_t dupf(float x) {
    uint32_t u = __float_as_uint(x); return pk2(u, u);
}

// ------------------------- 1) per-channel spatial mean of Y ------------------
__global__ void k_mean(const float* __restrict__ Y) {
    int bc = blockIdx.x, tid = threadIdx.x;
    const float* p = Y + (size_t)bc * NSP;
    float s = 0.0f;
#pragma unroll
    for (int j = 0; j < 16; j++) s += p[tid + j * 256];
    __shared__ float red[256];
    red[tid] = s; __syncthreads();
    for (int off = 128; off > 0; off >>= 1) {
        if (tid < off) red[tid] += red[tid + off];
        __syncthreads();
    }
    if (tid == 0) g_ymean[bc] = red[0] * (1.0f / NSP);
}

// --------- 2) fused: center, norm, transpose to [n][c'] bf16 -----------------
#define PREP_SMEM (2 * 256 * 33 * 4)
__global__ void __launch_bounds__(256) k_prep(const float* __restrict__ X,
                                              const float* __restrict__ Y) {
    extern __shared__ float dsm[];
    float* fx = dsm;                 // [256][33]
    float* fy = dsm + 256 * 33;      // [256][33]
    __shared__ float psx[8][32], psy[8][32], rnx_s[32], rny_s[32];

    int b = blockIdx.y;
    int n0 = blockIdx.x * 32;
    int tid = threadIdx.x;
    int n = tid & 31;
    int c8 = tid >> 5;               // 0..7

    float sx = 0.0f, sy = 0.0f;
#pragma unroll 4
    for (int pass = 0; pass < 32; pass++) {
        int c = pass * 8 + c8;
        float m = g_ymean[b * CC + c];
        size_t src = ((size_t)(b * CC + c) << 12) + n0 + n;
        float xv = X[src] - m;
        float yv = Y[src] - m;
        fx[c * 33 + n] = xv;
        fy[c * 33 + n] = yv;
        sx = fmaf(xv, xv, sx);
        sy = fmaf(yv, yv, sy);
    }
    psx[c8][n] = sx;
    psy[c8][n] = sy;
    __syncthreads();
    if (tid < 32) {
        float tx = 0.0f, ty = 0.0f;
#pragma unroll
        for (int i = 0; i < 8; i++) { tx += psx[i][tid]; ty += psy[i][tid]; }
        rnx_s[tid] = 1.0f / (sqrtf(tx) + EPSN);
        rny_s[tid] = 1.0f / (sqrtf(ty) + EPSN);
    }
    __syncthreads();

    // Paired writes: channels (2q, 2q+1) land at adjacent permuted slots.
    int k0 = (tid & 15) * 2;
    int pe = (((k0 >> 1) & 3) << 3) | (((k0 >> 4) & 1) << 2) | (((k0 >> 3) & 1) << 1);
#pragma unroll
    for (int pass = 0; pass < 2; pass++) {
        int nn = (tid >> 4) + pass * 16;     // 0..31
        float rx = rnx_s[nn], ry = rny_s[nn];
        size_t base = ((size_t)((b << 12) + n0 + nn)) << 8;
#pragma unroll
        for (int cg = 0; cg < 8; cg++) {
            int c = k0 + cg * 32;
            int cp = (cg * 32) | pe;
            uint32_t vx = pack_bf16x2(fx[c * 33 + nn] * rx, fx[(c + 1) * 33 + nn] * rx);
            uint32_t vy = pack_bf16x2(fy[c * 33 + nn] * ry, fy[(c + 1) * 33 + nn] * ry);
            *(uint32_t*)(g_Xt + base + cp) = vx;
            *(uint32_t*)(g_Yt + base + cp) = vy;
        }
    }
}

// ------------------- 3) bf16 mma.sync GEMM, 64x64 warp tiles -----------------
#define TILE_B   16384          // bytes per 128x64 bf16 tile
#define SMA(st)  ((st) * 2 * TILE_B)
#define SMB(st)  ((st) * 2 * TILE_B + TILE_B)
#define SM_TOT   (4 * TILE_B)   // 64 KB

__global__ void __launch_bounds__(128, 2) k_gemm_mma() {
    extern __shared__ char sm[];
    uint32_t sb = smem_u32(sm);
    int tid = threadIdx.x;
    int l = tid & 31, w = tid >> 5;
    int warpM = w >> 1, warpN = w & 1;
    int b = blockIdx.z;
    int n0 = blockIdx.y * 128, m0 = blockIdx.x * 128;

    const char* Ab = (const char*)(g_Xt + ((size_t)((b << 12) + n0)) * CC);
    const char* Bb = (const char*)(g_Yt + ((size_t)((b << 12) + m0)) * CC);

    int lr = tid >> 3;          // 0..15: row within 16-row pass
    int lc = tid & 7;           // 16B chunk within 128B row

    float acc[4][8][4];
#pragma unroll
    for (int i = 0; i < 4; i++)
#pragma unroll
        for (int j = 0; j < 8; j++)
#pragma unroll
            for (int q = 0; q < 4; q++) acc[i][j][q] = 0.0f;

    auto load = [&](int kc, int st) {
#pragma unroll
        for (int it = 0; it < 8; it++) {
            int row = lr + it * 16;
            uint32_t sw = (uint32_t)((lc ^ ((row & 1) << 2)) << 4);
            CP_ASYNC16(sb + SMA(st) + row * 128 + sw, Ab + (size_t)row * 512 + kc * 128 + lc * 16);
            CP_ASYNC16(sb + SMB(st) + row * 128 + sw, Bb + (size_t)row * 512 + kc * 128 + lc * 16);
        }
    };

    load(0, 0); CP_COMMIT();

    for (int kc = 0; kc < 4; kc++) {
        int st = kc & 1;
        CP_WAIT(0);
        __syncthreads();
        if (kc + 1 < 4) { load(kc + 1, st ^ 1); CP_COMMIT(); }

#pragma unroll
        for (int g = 0; g < 2; g++) {
            uint4 Af[4][2];
            uint4 Bf[8];
#pragma unroll
            for (int mi = 0; mi < 4; mi++)
#pragma unroll
                for (int h = 0; h < 2; h++) {
                    int r = warpM * 64 + mi * 16 + (l >> 2) + h * 8;
                    int ch = (g * 4 + (l & 3)) ^ ((r & 1) << 2);
                    Af[mi][h] = *(const uint4*)(sm + SMA(st) + r * 128 + ch * 16);
                }
#pragma unroll
            for (int ni = 0; ni < 8; ni++) {
                int r = warpN * 64 + ni * 8 + (l >> 2);
                int ch = (g * 4 + (l & 3)) ^ ((r & 1) << 2);
                Bf[ni] = *(const uint4*)(sm + SMB(st) + r * 128 + ch * 16);
            }

#pragma unroll
            for (int mi = 0; mi < 4; mi++)
#pragma unroll
                for (int ni = 0; ni < 8; ni++)
                    mma_bf16(acc[mi][ni], Af[mi][0].x, Af[mi][1].x, Af[mi][0].y, Af[mi][1].y,
                             Bf[ni].x, Bf[ni].y);
#pragma unroll
            for (int mi = 0; mi < 4; mi++)
#pragma unroll
                for (int ni = 0; ni < 8; ni++)
                    mma_bf16(acc[mi][ni], Af[mi][0].z, Af[mi][1].z, Af[mi][0].w, Af[mi][1].w,
                             Bf[ni].z, Bf[ni].w);
        }
    }

    // --- epilogue: write S as bf16, streaming (read-once downstream) ---
    __nv_bfloat16* Sp = g_S + (size_t)b * NSP * NSP;
#pragma unroll
    for (int mi = 0; mi < 4; mi++) {
        int r = n0 + warpM * 64 + mi * 16 + (l >> 2);
#pragma unroll
        for (int ni = 0; ni < 8; ni++) {
            int cg = m0 + warpN * 64 + ni * 8 + ((l & 3) << 1);
            __stcs((uint32_t*)(Sp + (size_t)r * NSP + cg),
                   pack_bf16x2(acc[mi][ni][0], acc[mi][ni][1]));
            __stcs((uint32_t*)(Sp + (size_t)(r + 8) * NSP + cg),
                   pack_bf16x2(acc[mi][ni][2], acc[mi][ni][3]));
        }
    }
}

// ------------------------- 4) per-row: max (bf16x2) -> exp-sum ---------------
// 128 threads/row, 32 elements/thread: 4 front-batched LDG.128 (MLP) and
// half the block-tail overhead of the 256-thread variant.
__global__ void k_reduce() {
    int row = blockIdx.x, tid = threadIdx.x;
    int l = tid & 31, w = tid >> 5;        // w: 0..3
    const uint4* p = (const uint4*)(g_S + (size_t)row * NSP);
    uint4 v0 = __ldcs(p + tid);
    uint4 v1 = __ldcs(p + tid + 128);
    uint4 v2 = __ldcs(p + tid + 256);
    uint4 v3 = __ldcs(p + tid + 384);
    uint32_t u[16] = { v0.x, v0.y, v0.z, v0.w, v1.x, v1.y, v1.z, v1.w,
                       v2.x, v2.y, v2.z, v2.w, v3.x, v3.y, v3.z, v3.w };

    // --- row max via packed bf16x2 max ---
    uint32_t mx2 = u[0];
#pragma unroll
    for (int j = 1; j < 16; j++) mx2 = max_bf16x2(mx2, u[j]);
    float mx = fmaxf(__uint_as_float(mx2 << 16),
                     __uint_as_float(mx2 & 0xffff0000u));
#pragma unroll
    for (int off = 16; off > 0; off >>= 1)
        mx = fmaxf(mx, __shfl_xor_sync(0xffffffffu, mx, off));
    __shared__ float red[4];
    __shared__ float bcast;
    if (l == 0) red[w] = mx;
    __syncthreads();
    if (tid == 0) {
        float m = fmaxf(fmaxf(red[0], red[1]), fmaxf(red[2], red[3]));
        bcast = m;
    }
    __syncthreads();
    float smax = bcast;

    // weight = 2^(s*kk2 + c2), packed f32x2 math
    float kk2 = 14.4269504089f / (1.001f - smax);          // 10*log2(e)/c
    float c2f = (0.001f - smax) * kk2;
    const float MAGIC = 12582912.0f;                       // 1.5 * 2^23
    const int ZCLAMP = 0x4B400000 - 126;                   // bits(MAGIC) - 126

    uint64_t K2  = dupf(kk2), C2 = dupf(c2f), M2 = dupf(MAGIC);
    uint64_t NM2 = dupf(-MAGIC), N1 = dupf(-1.0f);
    uint64_t P4 = dupf(9.618129e-3f), P3 = dupf(5.550411e-2f);
    uint64_t P2 = dupf(2.402265e-1f), P1 = dupf(6.931472e-1f), ONE = dupf(1.0f);

    float sumA = 0.0f, sumB = 0.0f;
#pragma unroll
    for (int j = 0; j < 16; j++) {
        uint64_t s2 = pk2(u[j] << 16, u[j] & 0xffff0000u);
        uint64_t y2 = fma2(s2, K2, C2);
        uint64_t z2 = add2(y2, M2);        // magic-rounded
        uint64_t d2 = add2(z2, NM2);       // rint(y)
        uint64_t t2 = fma2(d2, N1, y2);    // frac in [-0.5, 0.5]
        uint64_t q2 = fma2(t2, P4, P3);
        q2 = fma2(t2, q2, P2);
        q2 = fma2(t2, q2, P1);
        q2 = fma2(t2, q2, ONE);
        uint32_t zl, zh, ql, qh;
        upk2(z2, zl, zh);
        upk2(q2, ql, qh);
        int kl = max((int)zl, ZCLAMP);
        int kh = max((int)zh, ZCLAMP);
        uint32_t scl = ((uint32_t)kl << 23) + 0x3F800000u;
        uint32_t sch = ((uint32_t)kh << 23) + 0x3F800000u;
        sumA = fmaf(__uint_as_float(ql), __uint_as_float(scl), sumA);
        sumB = fmaf(__uint_as_float(qh), __uint_as_float(sch), sumB);
    }
    float sum = sumA + sumB;
#pragma unroll
    for (int off = 16; off > 0; off >>= 1)
        sum += __shfl_xor_sync(0xffffffffu, sum, off);
    if (l == 0) red[w] = sum;
    __syncthreads();
    if (tid == 0) {
        float tsum = red[0] + red[1] + red[2] + red[3];
        g_maxA[row] = exp2f(0.001f * kk2) / tsum;
    }
}

// ------------------------- 5) loss -------------------------------------------
__global__ void k_final(float* __restrict__ out) {
    int b = blockIdx.x, tid = threadIdx.x;
    float s = 0.0f;
#pragma unroll
    for (int j = 0; j < 16; j++) s += g_maxA[b * NSP + tid + j * 256];
    __shared__ float red[256];
    red[tid] = s; __syncthreads();
    for (int off = 128; off > 0; off >>= 1) {
        if (tid < off) red[tid] += red[tid + off];
        __syncthreads();
    }
    if (tid == 0) out[b] = -logf(red[0] * (1.0f / NSP));
}

// ------------------------- launch --------------------------------------------
extern "C" void kernel_launch(void* const* d_in, const int* in_sizes, int n_in,
                              void* d_out, int out_size) {
    const float* X = (const float*)d_in[0];
    const float* Y = (const float*)d_in[1];
    float* out = (float*)d_out;

    cudaFuncSetAttribute(k_prep, cudaFuncAttributeMaxDynamicSharedMemorySize, PREP_SMEM);
    cudaFuncSetAttribute(k_gemm_mma, cudaFuncAttributeMaxDynamicSharedMemorySize, SM_TOT);

    k_mean<<<BB * CC, 256>>>(Y);
    k_prep<<<dim3(NSP / 32, BB), 256, PREP_SMEM>>>(X, Y);
    k_gemm_mma<<<dim3(NSP / 128, NSP / 128, BB), 128, SM_TOT>>>();
    k_reduce<<<BB * NSP, 128>>>();
    k_final<<<BB, 256>>>(out);
}